// round 7
// baseline (speedup 1.0000x reference)
#include <cuda_runtime.h>
#include <math.h>
#include <stdint.h>

#define BATCH 512
#define DIN   128
#define HIDN  256
#define CSIZE 4
#define BC    16
#define CPC   64
#define NCTA  128
#define NT    512
#define KSPL  8

// smem float offsets
#define OFF_HID0 0            /* [16][256][2] dup hidden buf0 : 32KB */
#define OFF_HID1 8192         /* buf1                         : 32KB */
#define OFF_X0   16384        /* [16][128] x buf0             :  8KB */
#define OFF_X1   18432        /* x buf1                       :  8KB */
#define OFF_PAH  20480        /* ull [8][16][64] (A,H)        : 64KB */
#define OFF_PX   36864        /* float [8][16][64] X          : 32KB */
#define OFF_MB   45056        /* mbarrier (8B) + pad          */
#define SMEM_FLOATS 45064
#define SMEM_BYTES  (SMEM_FLOATS * 4)   /* 180256 */

typedef unsigned long long ull;

__device__ __forceinline__ ull ffma2(ull a, ull b, ull c) {
    ull d;
    asm("fma.rn.f32x2 %0, %1, %2, %3;" : "=l"(d) : "l"(a), "l"(b), "l"(c));
    return d;
}
__device__ __forceinline__ ull add2(ull a, ull b) {
    ull d;
    asm("add.rn.f32x2 %0, %1, %2;" : "=l"(d) : "l"(a), "l"(b));
    return d;
}
__device__ __forceinline__ ull pack2(float x, float y) {
    ull d;
    asm("mov.b64 %0, {%1, %2};" : "=l"(d) : "f"(x), "f"(y));
    return d;
}
__device__ __forceinline__ void unpack2(ull a, float& x, float& y) {
    asm("mov.b64 {%0, %1}, %2;" : "=f"(x), "=f"(y) : "l"(a));
}
__device__ __forceinline__ uint32_t smem_u32(const void* p) {
    uint32_t a;
    asm("{ .reg .u64 t; cvta.to.shared.u64 t, %1; cvt.u32.u64 %0, t; }"
        : "=r"(a) : "l"(p));
    return a;
}
__device__ __forceinline__ void cluster_sync_() {
    asm volatile("barrier.cluster.arrive.aligned;" ::: "memory");
    asm volatile("barrier.cluster.wait.aligned;" ::: "memory");
}
__device__ __forceinline__ void mbar_init(uint32_t a, uint32_t cnt) {
    asm volatile("mbarrier.init.shared.b64 [%0], %1;" :: "r"(a), "r"(cnt) : "memory");
}
__device__ __forceinline__ void mbar_arrive_cluster(uint32_t a) {
    asm volatile("mbarrier.arrive.release.cluster.shared::cluster.b64 _, [%0];"
                 :: "r"(a) : "memory");
}
__device__ __forceinline__ void mbar_wait(uint32_t a, uint32_t par) {
    asm volatile(
        "{\n\t.reg .pred P;\n\t"
        "WL%=:\n\t"
        "mbarrier.try_wait.parity.acquire.cluster.shared::cta.b64 P, [%0], %1, 0x989680;\n\t"
        "@P bra WD%=;\n\t"
        "bra WL%=;\n\t"
        "WD%=:\n\t}"
        :: "r"(a), "r"(par) : "memory");
}

__global__ __launch_bounds__(NT, 1) __cluster_dims__(CSIZE, 1, 1)
void rnn_kernel(const float* __restrict__ data,
                const float* __restrict__ ih_w,
                const float* __restrict__ ih_b,
                const float* __restrict__ hh_w,
                const float* __restrict__ hh_b,
                const int*   __restrict__ lengths,
                float*       __restrict__ out)
{
    extern __shared__ float smem[];
    ull*   s_pAH = (ull*)(smem + OFF_PAH);
    float* s_pX  = smem + OFF_PX;

    const int tid = threadIdx.x;
    uint32_t r;
    asm("mov.u32 %0, %%cluster_ctarank;" : "=r"(r));
    const int B0  = (blockIdx.x >> 2) * BC;
    const int cl  = tid & 63;
    const int kq  = tid >> 6;          // 0..7
    const int gc  = (int)r * CPC + cl;
    const int k0  = kq * 32;
    const int ik0 = kq * 16;

    // ---- persistent register weights ----
    ull whh2[32];
    #pragma unroll
    for (int i = 0; i < 32; i++) {
        float wa = hh_w[gc * HIDN + k0 + i];
        float wh = hh_w[(gc + HIDN) * HIDN + k0 + i];
        whh2[i] = pack2(wa, wh);
    }
    float wih_r[16];
    #pragma unroll
    for (int i = 0; i < 16; i++) wih_r[i] = ih_w[gc * DIN + ik0 + i];

    // zero both hidden buffers
    for (int i = tid; i < 16384; i += NT) smem[i] = 0.0f;

    const float bA = hh_b[gc];
    const float bH = hh_b[gc + HIDN];
    const float bX = ih_b[gc];

    int len2[2];
    #pragma unroll
    for (int j = 0; j < 2; j++) len2[j] = lengths[B0 + kq * 2 + j];
    int cap = 1;
    for (int i = 0; i < BC; i++) cap = max(cap, lengths[B0 + i]);

    // remote smem bases of all 4 CTAs
    const uint32_t h0 = smem_u32(smem);
    uint32_t rb[CSIZE];
    #pragma unroll
    for (int d = 0; d < CSIZE; d++)
        asm("mapa.shared::cluster.u32 %0, %1, %2;" : "=r"(rb[d]) : "r"(h0), "r"(d));
    const uint32_t mb_local = h0 + OFF_MB * 4;

    if (tid == 0) mbar_init(mb_local, 64);   // 16 warps x 4 CTAs per phase

    // stage x(0) into buf0; prefetch x(1)
    ((float4*)(smem + OFF_X0))[tid] =
        ((const float4*)(data + (size_t)0 * BATCH * DIN + (size_t)B0 * DIN))[tid];
    float4 xp = ((const float4*)(data + (size_t)1 * BATCH * DIN + (size_t)B0 * DIN))[tid];

    __syncthreads();
    cluster_sync_();   // zeros + mbar init + x0 visible cluster-wide

    for (int t = 0; t < cap; ++t) {
        const float* cur    = smem + ((t & 1) ? OFF_HID1 : OFF_HID0);
        const float* sx_cur = smem + ((t & 1) ? OFF_X1 : OFF_X0);
        float*       sx_nxt = smem + ((t & 1) ? OFF_X0 : OFF_X1);
        const uint32_t nxtoff = ((t + 1) & 1) * 32768u;

        // ================= phase 1: compute partials b 0..7 =================
        #pragma unroll 2
        for (int b = 0; b < 8; b++) {
            const float* hb = cur + b * 512 + k0 * 2;
            ull a0 = 0ull, a1 = 0ull, a2 = 0ull, a3 = 0ull;
            #pragma unroll
            for (int i = 0; i < 16; i++) {
                ulonglong2 hd = *(const ulonglong2*)(hb + 4 * i);
                if (i & 1) {
                    a2 = ffma2(hd.x, whh2[2 * i],     a2);
                    a3 = ffma2(hd.y, whh2[2 * i + 1], a3);
                } else {
                    a0 = ffma2(hd.x, whh2[2 * i],     a0);
                    a1 = ffma2(hd.y, whh2[2 * i + 1], a1);
                }
            }
            const float* xb = sx_cur + b * 128 + ik0;
            float x0 = 0.f, x1 = 0.f, x2 = 0.f, x3 = 0.f;
            #pragma unroll
            for (int i = 0; i < 4; i++) {
                float4 xv = *(const float4*)(xb + 4 * i);
                x0 = fmaf(xv.x, wih_r[4 * i + 0], x0);
                x1 = fmaf(xv.y, wih_r[4 * i + 1], x1);
                x2 = fmaf(xv.z, wih_r[4 * i + 2], x2);
                x3 = fmaf(xv.w, wih_r[4 * i + 3], x3);
            }
            s_pAH[(kq * 16 + b) * 64 + cl] = add2(add2(a0, a2), add2(a1, a3));
            s_pX [(kq * 16 + b) * 64 + cl] = (x0 + x1) + (x2 + x3);
        }
        __syncthreads();   // bar1: half-1 partials visible

        // ====== phase 2: compute b 8..15  ||  finalize b0..7 (kq<4)  ========
        // stage x(t+1), prefetch x(t+2)  (overlaps compute)
        ((float4*)sx_nxt)[tid] = xp;
        if (t + 2 < cap)
            xp = ((const float4*)(data + ((size_t)(t + 2) * BATCH + B0) * DIN))[tid];

        #pragma unroll 2
        for (int b = 8; b < 16; b++) {
            const float* hb = cur + b * 512 + k0 * 2;
            ull a0 = 0ull, a1 = 0ull, a2 = 0ull, a3 = 0ull;
            #pragma unroll
            for (int i = 0; i < 16; i++) {
                ulonglong2 hd = *(const ulonglong2*)(hb + 4 * i);
                if (i & 1) {
                    a2 = ffma2(hd.x, whh2[2 * i],     a2);
                    a3 = ffma2(hd.y, whh2[2 * i + 1], a3);
                } else {
                    a0 = ffma2(hd.x, whh2[2 * i],     a0);
                    a1 = ffma2(hd.y, whh2[2 * i + 1], a1);
                }
            }
            const float* xb = sx_cur + b * 128 + ik0;
            float x0 = 0.f, x1 = 0.f, x2 = 0.f, x3 = 0.f;
            #pragma unroll
            for (int i = 0; i < 4; i++) {
                float4 xv = *(const float4*)(xb + 4 * i);
                x0 = fmaf(xv.x, wih_r[4 * i + 0], x0);
                x1 = fmaf(xv.y, wih_r[4 * i + 1], x1);
                x2 = fmaf(xv.z, wih_r[4 * i + 2], x2);
                x3 = fmaf(xv.w, wih_r[4 * i + 3], x3);
            }
            s_pAH[(kq * 16 + b) * 64 + cl] = add2(add2(a0, a2), add2(a1, a3));
            s_pX [(kq * 16 + b) * 64 + cl] = (x0 + x1) + (x2 + x3);
        }

        // finalize: thread owns outputs (b = kq*2 + j, col gc); kq<4 -> b<8
        if (kq < 4) {
            #pragma unroll
            for (int j = 0; j < 2; j++) {
                int b = kq * 2 + j;
                ull sAH = s_pAH[(0 * 16 + b) * 64 + cl];
                float sX = s_pX[(0 * 16 + b) * 64 + cl];
                #pragma unroll
                for (int q = 1; q < KSPL; q++) {
                    sAH = add2(sAH, s_pAH[(q * 16 + b) * 64 + cl]);
                    sX += s_pX[(q * 16 + b) * 64 + cl];
                }
                float A, H;
                unpack2(sAH, A, H);
                A += bA; H += bH;
                float alpha = 1.0f / (1.0f + expf(-A));
                float hs    = (exp2f(alpha * H) - 1.0f) / alpha + alpha;
                float nh    = tanhf(sX + bX + hs);
                float oldv  = cur[b * 512 + 2 * gc];
                float w     = (t < len2[j]) ? nh : oldv;
                uint32_t v  = __float_as_uint(w);
                ull v2;
                asm("mov.b64 %0, {%1, %1};" : "=l"(v2) : "r"(v));
                uint32_t boff = nxtoff + (uint32_t)((b * 512 + 2 * gc) * 4);
                #pragma unroll
                for (int d = 0; d < CSIZE; d++)
                    asm volatile("st.shared::cluster.u64 [%0], %1;"
                                 :: "r"(rb[d] + boff), "l"(v2) : "memory");
            }
        }
        __syncthreads();   // bar2: half-2 partials visible

        if (kq >= 4) {
            #pragma unroll
            for (int j = 0; j < 2; j++) {
                int b = kq * 2 + j;
                ull sAH = s_pAH[(0 * 16 + b) * 64 + cl];
                float sX = s_pX[(0 * 16 + b) * 64 + cl];
                #pragma unroll
                for (int q = 1; q < KSPL; q++) {
                    sAH = add2(sAH, s_pAH[(q * 16 + b) * 64 + cl]);
                    sX += s_pX[(q * 16 + b) * 64 + cl];
                }
                float A, H;
                unpack2(sAH, A, H);
                A += bA; H += bH;
                float alpha = 1.0f / (1.0f + expf(-A));
                float hs    = (exp2f(alpha * H) - 1.0f) / alpha + alpha;
                float nh    = tanhf(sX + bX + hs);
                float oldv  = cur[b * 512 + 2 * gc];
                float w     = (t < len2[j]) ? nh : oldv;
                uint32_t v  = __float_as_uint(w);
                ull v2;
                asm("mov.b64 %0, {%1, %1};" : "=l"(v2) : "r"(v));
                uint32_t boff = nxtoff + (uint32_t)((b * 512 + 2 * gc) * 4);
                #pragma unroll
                for (int d = 0; d < CSIZE; d++)
                    asm volatile("st.shared::cluster.u64 [%0], %1;"
                                 :: "r"(rb[d] + boff), "l"(v2) : "memory");
            }
        }

        // one arrive per warp per destination CTA (release covers pre-bar2
        // stores via barrier happens-before + own stores via program order)
        if ((tid & 31) == 0) {
            #pragma unroll
            for (int d = 0; d < CSIZE; d++)
                mbar_arrive_cluster(rb[d] + OFF_MB * 4);
        }
        mbar_wait(mb_local, (uint32_t)(t & 1));   // acquire: all stores visible
    }

    // final state in buffer (cap & 1)
    const float* fin = smem + ((cap & 1) ? OFF_HID1 : OFF_HID0);
    #pragma unroll
    for (int j = 0; j < 2; j++) {
        int b = kq * 2 + j;
        out[(size_t)(B0 + b) * HIDN + gc] = fin[b * 512 + 2 * gc];
    }
}

extern "C" void kernel_launch(void* const* d_in, const int* in_sizes, int n_in,
                              void* d_out, int out_size)
{
    (void)in_sizes; (void)n_in; (void)out_size;
    const float* data    = (const float*)d_in[0];   // [1024,512,128]
    const float* ih_w    = (const float*)d_in[1];   // [256,128]
    const float* ih_b    = (const float*)d_in[2];   // [256]
    const float* hh_w    = (const float*)d_in[3];   // [512,256]
    const float* hh_b    = (const float*)d_in[4];   // [512]
    const int*   lengths = (const int*)d_in[5];     // [512]
    float*       out     = (float*)d_out;           // [1,512,256]

    cudaFuncSetAttribute(rnn_kernel,
                         cudaFuncAttributeMaxDynamicSharedMemorySize, SMEM_BYTES);
    rnn_kernel<<<NCTA, NT, SMEM_BYTES>>>(data, ih_w, ih_b, hh_w, hh_b, lengths, out);
}

// round 10
// speedup vs baseline: 2.1603x; 2.1603x over previous
#include <cuda_runtime.h>
#include <cuda_bf16.h>
#include <math.h>
#include <stdint.h>

#define BATCH 512
#define DIN   128
#define HIDN  256
#define CSIZE 4
#define NT    512
#define NCTA  128   /* 32 clusters x 4 CTAs */

// hidden buffer: [16 n][260 words] packed (hi|lo<<16) bf16 pair; padded 256->260
#define HROW   260
#define HBUF_B (16 * HROW * 4)        /* 16640 B per buffer */

// smem byte layout
#define OB_H    0                     /* 2 buffers: 33280 B */
#define OB_SD   33280                 /* f32 [2 kh][128 m][18 n] = 18432 B */
#define OB_PX   51712                 /* f32 [8][16][64] = 32768 B */
#define OB_X    84480                 /* f32 [16][128]   =  8192 B */
#define OB_HOUT 92672                 /* f32 [16][64]    =  4096 B */
#define SMEM_BYTES 96768

#define SD(kh, m, n) ((((kh) * 128 + (m)) * 18) + (n))

__device__ __forceinline__ uint32_t smem_u32(const void* p) {
    uint32_t a;
    asm("{ .reg .u64 t; cvta.to.shared.u64 t, %1; cvt.u32.u64 %0, t; }" : "=r"(a) : "l"(p));
    return a;
}
__device__ __forceinline__ void cluster_sync_() {
    asm volatile("barrier.cluster.arrive.aligned;" ::: "memory");
    asm volatile("barrier.cluster.wait.aligned;" ::: "memory");
}
__device__ __forceinline__ void mma_bf16(float* d, const uint32_t* a, uint32_t b0, uint32_t b1) {
    asm volatile(
        "mma.sync.aligned.m16n8k16.row.col.f32.bf16.bf16.f32 "
        "{%0,%1,%2,%3}, {%4,%5,%6,%7}, {%8,%9}, {%0,%1,%2,%3};"
        : "+f"(d[0]), "+f"(d[1]), "+f"(d[2]), "+f"(d[3])
        : "r"(a[0]), "r"(a[1]), "r"(a[2]), "r"(a[3]), "r"(b0), "r"(b1));
}
__device__ __forceinline__ unsigned short bfbits(__nv_bfloat16 v) {
    return *(unsigned short*)&v;
}

__global__ __launch_bounds__(NT, 1) __cluster_dims__(CSIZE, 1, 1)
void rnn_kernel(const float* __restrict__ data,
                const float* __restrict__ ih_w,
                const float* __restrict__ ih_b,
                const float* __restrict__ hh_w,
                const float* __restrict__ hh_b,
                const int*   __restrict__ lengths,
                float*       __restrict__ out)
{
    extern __shared__ char sm[];
    uint32_t* s_h  = (uint32_t*)(sm + OB_H);     // two buffers of HBUF_B
    float*    s_sd = (float*)(sm + OB_SD);
    float*    s_pX = (float*)(sm + OB_PX);
    float*    s_x  = (float*)(sm + OB_X);
    float*    s_hO = (float*)(sm + OB_HOUT);

    const int tid  = threadIdx.x;
    const int wid  = tid >> 5;
    const int lane = tid & 31;
    const int g    = lane >> 2;        // groupID
    const int t4   = lane & 3;         // threadID in group
    uint32_t r;
    asm("mov.u32 %0, %%cluster_ctarank;" : "=r"(r));
    const int B0  = (blockIdx.x >> 2) * 16;
    const int cl  = tid & 63;          // owned column (local)
    const int kq  = tid >> 6;          // 0..7 (k-eighth for xw partials)
    const int gc  = (int)r * 64 + cl;  // global hidden col
    const int ik0 = kq * 16;

    const int M0  = (wid >> 1) * 16;   // warp's M slice
    const int khb = wid & 1;           // warp's K half
    const int K0c = khb * 128;

    // ---- persistent A fragments (bf16 hi/lo split) in registers ----
    // A[m][k]: m<64 -> alpha row (hh_w row r*64+m); m>=64 -> h row (hh_w row 256+r*64+m-64)
    uint32_t Ahi[8][4], Alo[8][4];
    #pragma unroll
    for (int ks = 0; ks < 8; ks++) {
        #pragma unroll
        for (int rg = 0; rg < 4; rg++) {
            int m = M0 + g + ((rg & 1) ? 8 : 0);
            int c = K0c + ks * 16 + 2 * t4 + ((rg >= 2) ? 8 : 0);
            int grow = (m < 64) ? ((int)r * 64 + m) : (HIDN + (int)r * 64 + (m - 64));
            float w0 = hh_w[grow * HIDN + c];
            float w1 = hh_w[grow * HIDN + c + 1];
            __nv_bfloat16 h0 = __float2bfloat16(w0);
            __nv_bfloat16 h1 = __float2bfloat16(w1);
            __nv_bfloat16 l0 = __float2bfloat16(w0 - __bfloat162float(h0));
            __nv_bfloat16 l1 = __float2bfloat16(w1 - __bfloat162float(h1));
            Ahi[ks][rg] = (uint32_t)bfbits(h0) | ((uint32_t)bfbits(h1) << 16);
            Alo[ks][rg] = (uint32_t)bfbits(l0) | ((uint32_t)bfbits(l1) << 16);
        }
    }

    // ih register weights + biases
    float wih_r[16];
    #pragma unroll
    for (int i = 0; i < 16; i++) wih_r[i] = ih_w[gc * DIN + ik0 + i];
    const float bA = hh_b[gc];
    const float bH = hh_b[gc + HIDN];
    const float bX = ih_b[gc];

    int len2[2];
    #pragma unroll
    for (int j = 0; j < 2; j++) len2[j] = lengths[B0 + kq * 2 + j];
    int cap = 1;
    for (int i = 0; i < 16; i++) cap = max(cap, lengths[B0 + i]);

    // zero both hidden buffers (h0 = 0 -> packed word 0)
    for (int i = tid; i < 2 * 16 * HROW; i += NT) s_h[i] = 0u;

    const uint32_t smb = smem_u32(sm);
    uint32_t rb[CSIZE];
    #pragma unroll
    for (int d = 0; d < CSIZE; d++)
        asm("mapa.shared::cluster.u32 %0, %1, %2;" : "=r"(rb[d]) : "r"(smb), "r"(d));

    __syncthreads();
    cluster_sync_();   // all CTAs zeroed before any peer store arrives

    float4 xp = ((const float4*)(data + (size_t)B0 * DIN))[tid];

    for (int t = 0; t < cap; ++t) {
        const uint32_t* cur = s_h + (t & 1) * (16 * HROW);
        const uint32_t  nxtoff = (uint32_t)OB_H + (uint32_t)(((t + 1) & 1) * HBUF_B);

        // stage x_t  ([b][k] fp32)
        ((float4*)s_x)[tid] = xp;
        __syncthreads();
        if (t + 1 < cap)
            xp = ((const float4*)(data + ((size_t)(t + 1) * BATCH + B0) * DIN))[tid];

        // ================= HMMA: D = Whi*hhi + Wlo*hhi + Whi*hlo =============
        float dacc[2][4];
        #pragma unroll
        for (int nt = 0; nt < 2; nt++)
            #pragma unroll
            for (int i = 0; i < 4; i++) dacc[nt][i] = 0.0f;

        #pragma unroll
        for (int ks = 0; ks < 8; ks++) {
            #pragma unroll
            for (int nt = 0; nt < 2; nt++) {
                const uint32_t* hrow = cur + (nt * 8 + g) * HROW + K0c + ks * 16 + 2 * t4;
                uint2 wA = *(const uint2*)(hrow);       // k = 2t, 2t+1
                uint2 wB = *(const uint2*)(hrow + 8);   // k = 2t+8, 2t+9
                uint32_t bh0 = __byte_perm(wA.x, wA.y, 0x5410);
                uint32_t bl0 = __byte_perm(wA.x, wA.y, 0x7632);
                uint32_t bh1 = __byte_perm(wB.x, wB.y, 0x5410);
                uint32_t bl1 = __byte_perm(wB.x, wB.y, 0x7632);
                mma_bf16(dacc[nt], Ahi[ks], bh0, bh1);
                mma_bf16(dacc[nt], Alo[ks], bh0, bh1);
                mma_bf16(dacc[nt], Ahi[ks], bl0, bl1);
            }
        }

        // ---- xw partials on CUDA cores (fp32 exact) ----
        #pragma unroll 2
        for (int b = 0; b < 16; b++) {
            const float* xb = s_x + b * 128 + ik0;
            float x0 = 0.f, x1 = 0.f, x2 = 0.f, x3 = 0.f;
            #pragma unroll
            for (int i = 0; i < 4; i++) {
                float4 xv = *(const float4*)(xb + 4 * i);
                x0 = fmaf(xv.x, wih_r[4 * i + 0], x0);
                x1 = fmaf(xv.y, wih_r[4 * i + 1], x1);
                x2 = fmaf(xv.z, wih_r[4 * i + 2], x2);
                x3 = fmaf(xv.w, wih_r[4 * i + 3], x3);
            }
            s_pX[(kq * 16 + b) * 64 + cl] = (x0 + x1) + (x2 + x3);
        }

        // ---- store D fragments ----
        #pragma unroll
        for (int nt = 0; nt < 2; nt++) {
            int nb = nt * 8 + 2 * t4;
            *(float2*)&s_sd[SD(khb, M0 + g,     nb)] = make_float2(dacc[nt][0], dacc[nt][1]);
            *(float2*)&s_sd[SD(khb, M0 + g + 8, nb)] = make_float2(dacc[nt][2], dacc[nt][3]);
        }
        __syncthreads();   // D slabs + pX visible

        // ---- gate: thread owns (col gc, b = 2kq+j) ----
        #pragma unroll
        for (int j = 0; j < 2; j++) {
            int b = kq * 2 + j;
            float Apre = s_sd[SD(0, cl, b)] + s_sd[SD(1, cl, b)] + bA;
            float Hpre = s_sd[SD(0, 64 + cl, b)] + s_sd[SD(1, 64 + cl, b)] + bH;
            float xw = 0.f;
            #pragma unroll
            for (int q = 0; q < 8; q++) xw += s_pX[(q * 16 + b) * 64 + cl];
            float alpha = 1.0f / (1.0f + expf(-Apre));
            float hs    = (exp2f(alpha * Hpre) - 1.0f) / alpha + alpha;
            float nh    = tanhf(xw + bX + hs);

            uint32_t oldw = cur[b * HROW + gc];
            uint32_t word;
            if (t < len2[j]) {
                s_hO[b * 64 + cl] = nh;
                __nv_bfloat16 hi = __float2bfloat16(nh);
                __nv_bfloat16 lo = __float2bfloat16(nh - __bfloat162float(hi));
                word = (uint32_t)bfbits(hi) | ((uint32_t)bfbits(lo) << 16);
            } else {
                word = oldw;   // exact carry
            }
            uint32_t boff = nxtoff + (uint32_t)((b * HROW + gc) * 4);
            #pragma unroll
            for (int d = 0; d < CSIZE; d++)
                asm volatile("st.shared::cluster.b32 [%0], %1;"
                             :: "r"(rb[d] + boff), "r"(word) : "memory");
        }
        cluster_sync_();   // arrive=release: stores visible cluster-wide
    }

    // output (len >= 1 guarantees every (b, cl) was written at t=0)
    #pragma unroll
    for (int j = 0; j < 2; j++) {
        int b = kq * 2 + j;
        out[(size_t)(B0 + b) * HIDN + gc] = s_hO[b * 64 + cl];
    }
}

extern "C" void kernel_launch(void* const* d_in, const int* in_sizes, int n_in,
                              void* d_out, int out_size)
{
    (void)in_sizes; (void)n_in; (void)out_size;
    const float* data    = (const float*)d_in[0];   // [1024,512,128]
    const float* ih_w    = (const float*)d_in[1];   // [256,128]
    const float* ih_b    = (const float*)d_in[2];   // [256]
    const float* hh_w    = (const float*)d_in[3];   // [512,256]
    const float* hh_b    = (const float*)d_in[4];   // [512]
    const int*   lengths = (const int*)d_in[5];     // [512]
    float*       out     = (float*)d_out;           // [1,512,256]

    cudaFuncSetAttribute(rnn_kernel,
                         cudaFuncAttributeMaxDynamicSharedMemorySize, SMEM_BYTES);
    rnn_kernel<<<NCTA, NT, SMEM_BYTES>>>(data, ih_w, ih_b, hh_w, hh_b, lengths, out);
}

// round 11
// speedup vs baseline: 2.6178x; 1.2118x over previous
#include <cuda_runtime.h>
#include <cuda_bf16.h>
#include <math.h>
#include <stdint.h>

#define BATCH 512
#define DIN   128
#define HIDN  256
#define CSIZE 4
#define NT    512
#define NCTA  128   /* 32 clusters x 4 CTAs */

// hidden row: packed (hi|lo<<16) bf16 words; [h 256 | x 128] = 384 words, pad->388
// 388*4 = 1552 B; 1552 mod 128 = 16 -> conflict-free 8-row x 4-lane LDS pattern
#define HROW   388
#define HBUF_W (16 * HROW)            /* words per buffer */
#define HBUF_B (HBUF_W * 4)           /* 24832 B */

// smem byte layout
#define OB_H    0                     /* 2 buffers: 49664 B                     */
#define OB_SD   49664                 /* f32 [2 kh][128 m][18 n] = 18432 B      */
#define OB_SDX  68096                 /* f32 [4 kp][64 m][18 n]  = 18432 B      */
#define OB_HOUT 86528                 /* f32 [16][64] = 4096 B                  */
#define SMEM_BYTES 90624

#define SD(kh, m, n)  ((((kh) * 128 + (m)) * 18) + (n))
#define SDX(kp, m, n) ((((kp) * 64 + (m)) * 18) + (n))

__device__ __forceinline__ uint32_t smem_u32(const void* p) {
    uint32_t a;
    asm("{ .reg .u64 t; cvta.to.shared.u64 t, %1; cvt.u32.u64 %0, t; }" : "=r"(a) : "l"(p));
    return a;
}
__device__ __forceinline__ void cluster_sync_() {
    asm volatile("barrier.cluster.arrive.aligned;" ::: "memory");
    asm volatile("barrier.cluster.wait.aligned;" ::: "memory");
}
__device__ __forceinline__ void mma_bf16(float* d, const uint32_t* a, uint32_t b0, uint32_t b1) {
    asm volatile(
        "mma.sync.aligned.m16n8k16.row.col.f32.bf16.bf16.f32 "
        "{%0,%1,%2,%3}, {%4,%5,%6,%7}, {%8,%9}, {%0,%1,%2,%3};"
        : "+f"(d[0]), "+f"(d[1]), "+f"(d[2]), "+f"(d[3])
        : "r"(a[0]), "r"(a[1]), "r"(a[2]), "r"(a[3]), "r"(b0), "r"(b1));
}
__device__ __forceinline__ unsigned short bfbits(__nv_bfloat16 v) {
    return *(unsigned short*)&v;
}
__device__ __forceinline__ uint32_t packw(float f) {   // (hi | lo<<16)
    __nv_bfloat16 hi = __float2bfloat16(f);
    __nv_bfloat16 lo = __float2bfloat16(f - __bfloat162float(hi));
    return (uint32_t)bfbits(hi) | ((uint32_t)bfbits(lo) << 16);
}

__global__ __launch_bounds__(NT, 1) __cluster_dims__(CSIZE, 1, 1)
void rnn_kernel(const float* __restrict__ data,
                const float* __restrict__ ih_w,
                const float* __restrict__ ih_b,
                const float* __restrict__ hh_w,
                const float* __restrict__ hh_b,
                const int*   __restrict__ lengths,
                float*       __restrict__ out)
{
    extern __shared__ char sm[];
    uint32_t* s_h   = (uint32_t*)(sm + OB_H);
    float*    s_sd  = (float*)(sm + OB_SD);
    float*    s_sdx = (float*)(sm + OB_SDX);
    float*    s_hO  = (float*)(sm + OB_HOUT);

    const int tid  = threadIdx.x;
    const int wid  = tid >> 5;
    const int lane = tid & 31;
    const int g    = lane >> 2;
    const int t4   = lane & 3;
    uint32_t r;
    asm("mov.u32 %0, %%cluster_ctarank;" : "=r"(r));
    const int B0  = (blockIdx.x >> 2) * 16;
    const int cl  = tid & 63;
    const int kq  = tid >> 6;              // 0..7
    const int gc  = (int)r * 64 + cl;

    const int M0  = (wid >> 1) * 16;       // gate GEMM M slice
    const int khb = wid & 1;               // gate GEMM K half
    const int K0c = khb * 128;
    const int xms = wid >> 2;              // xw GEMM M slice (0..3)
    const int xkp = wid & 3;               // xw GEMM k-pair  (0..3)

    // ---- persistent gate A fragments (hh_w, bf16 hi/lo split) ----
    uint32_t Ahi[8][4], Alo[8][4];
    #pragma unroll
    for (int ks = 0; ks < 8; ks++) {
        #pragma unroll
        for (int rg = 0; rg < 4; rg++) {
            int m = M0 + g + ((rg & 1) ? 8 : 0);
            int c = K0c + ks * 16 + 2 * t4 + ((rg >= 2) ? 8 : 0);
            int grow = (m < 64) ? ((int)r * 64 + m) : (HIDN + (int)r * 64 + (m - 64));
            float w0 = hh_w[grow * HIDN + c];
            float w1 = hh_w[grow * HIDN + c + 1];
            __nv_bfloat16 h0 = __float2bfloat16(w0), h1 = __float2bfloat16(w1);
            __nv_bfloat16 l0 = __float2bfloat16(w0 - __bfloat162float(h0));
            __nv_bfloat16 l1 = __float2bfloat16(w1 - __bfloat162float(h1));
            Ahi[ks][rg] = (uint32_t)bfbits(h0) | ((uint32_t)bfbits(h1) << 16);
            Alo[ks][rg] = (uint32_t)bfbits(l0) | ((uint32_t)bfbits(l1) << 16);
        }
    }
    // ---- persistent xw A fragments (ih_w) ----
    uint32_t Xhi[2][4], Xlo[2][4];
    #pragma unroll
    for (int kk = 0; kk < 2; kk++) {
        int ks = 2 * xkp + kk;
        #pragma unroll
        for (int rg = 0; rg < 4; rg++) {
            int m = 16 * xms + g + ((rg & 1) ? 8 : 0);
            int c = ks * 16 + 2 * t4 + ((rg >= 2) ? 8 : 0);
            float w0 = ih_w[((int)r * 64 + m) * DIN + c];
            float w1 = ih_w[((int)r * 64 + m) * DIN + c + 1];
            __nv_bfloat16 h0 = __float2bfloat16(w0), h1 = __float2bfloat16(w1);
            __nv_bfloat16 l0 = __float2bfloat16(w0 - __bfloat162float(h0));
            __nv_bfloat16 l1 = __float2bfloat16(w1 - __bfloat162float(h1));
            Xhi[kk][rg] = (uint32_t)bfbits(h0) | ((uint32_t)bfbits(h1) << 16);
            Xlo[kk][rg] = (uint32_t)bfbits(l0) | ((uint32_t)bfbits(l1) << 16);
        }
    }

    const float bA = hh_b[gc];
    const float bH = hh_b[gc + HIDN];
    const float bX = ih_b[gc];

    int len2[2];
    #pragma unroll
    for (int j = 0; j < 2; j++) len2[j] = lengths[B0 + kq * 2 + j];
    int cap = 1;
    for (int i = 0; i < 16; i++) cap = max(cap, lengths[B0 + i]);

    // zero both hidden buffers
    for (int i = tid; i < 2 * HBUF_W; i += NT) s_h[i] = 0u;

    const uint32_t smb = smem_u32(sm);
    uint32_t rb[CSIZE];
    #pragma unroll
    for (int d = 0; d < CSIZE; d++)
        asm("mapa.shared::cluster.u32 %0, %1, %2;" : "=r"(rb[d]) : "r"(smb), "r"(d));

    // stage x(0) into buf0 (warp wid owns row wid; lane covers cols 4*lane..+3)
    {
        float4 x0 = ((const float4*)(data + (size_t)B0 * DIN))[tid];
        uint4 wv = make_uint4(packw(x0.x), packw(x0.y), packw(x0.z), packw(x0.w));
        *(uint4*)(s_h + wid * HROW + 256 + 4 * lane) = wv;
    }
    float4 xp = ((const float4*)(data + ((size_t)1 * BATCH + B0) * DIN))[tid];

    __syncthreads();
    cluster_sync_();   // zeros + x0 visible before any peer store / MMA

    for (int t = 0; t < cap; ++t) {
        const uint32_t* cur = s_h + (t & 1) * HBUF_W;
        uint32_t*       nxt = s_h + ((t + 1) & 1) * HBUF_W;
        const uint32_t  nxtoff = (uint32_t)OB_H + (uint32_t)(((t + 1) & 1) * HBUF_B);

        // ============ xw GEMM first (releases accumulators early) ============
        {
            float xacc[2][4];
            #pragma unroll
            for (int nt = 0; nt < 2; nt++)
                #pragma unroll
                for (int i = 0; i < 4; i++) xacc[nt][i] = 0.0f;
            #pragma unroll
            for (int kk = 0; kk < 2; kk++) {
                int ks = 2 * xkp + kk;
                #pragma unroll
                for (int nt = 0; nt < 2; nt++) {
                    const uint32_t* xrow = cur + (nt * 8 + g) * HROW + 256 + ks * 16 + 2 * t4;
                    uint2 wA = *(const uint2*)(xrow);
                    uint2 wB = *(const uint2*)(xrow + 8);
                    uint32_t bh0 = __byte_perm(wA.x, wA.y, 0x5410);
                    uint32_t bl0 = __byte_perm(wA.x, wA.y, 0x7632);
                    uint32_t bh1 = __byte_perm(wB.x, wB.y, 0x5410);
                    uint32_t bl1 = __byte_perm(wB.x, wB.y, 0x7632);
                    mma_bf16(xacc[nt], Xhi[kk], bh0, bh1);
                    mma_bf16(xacc[nt], Xlo[kk], bh0, bh1);
                    mma_bf16(xacc[nt], Xhi[kk], bl0, bl1);
                }
            }
            #pragma unroll
            for (int nt = 0; nt < 2; nt++) {
                int nb = nt * 8 + 2 * t4;
                *(float2*)&s_sdx[SDX(xkp, 16 * xms + g,     nb)] = make_float2(xacc[nt][0], xacc[nt][1]);
                *(float2*)&s_sdx[SDX(xkp, 16 * xms + g + 8, nb)] = make_float2(xacc[nt][2], xacc[nt][3]);
            }
        }

        // ================== gate GEMM: D = Whi*hhi + Wlo*hhi + Whi*hlo =======
        float dacc[2][4];
        #pragma unroll
        for (int nt = 0; nt < 2; nt++)
            #pragma unroll
            for (int i = 0; i < 4; i++) dacc[nt][i] = 0.0f;
        #pragma unroll
        for (int ks = 0; ks < 8; ks++) {
            #pragma unroll
            for (int nt = 0; nt < 2; nt++) {
                const uint32_t* hrow = cur + (nt * 8 + g) * HROW + K0c + ks * 16 + 2 * t4;
                uint2 wA = *(const uint2*)(hrow);
                uint2 wB = *(const uint2*)(hrow + 8);
                uint32_t bh0 = __byte_perm(wA.x, wA.y, 0x5410);
                uint32_t bl0 = __byte_perm(wA.x, wA.y, 0x7632);
                uint32_t bh1 = __byte_perm(wB.x, wB.y, 0x5410);
                uint32_t bl1 = __byte_perm(wB.x, wB.y, 0x7632);
                mma_bf16(dacc[nt], Ahi[ks], bh0, bh1);
                mma_bf16(dacc[nt], Alo[ks], bh0, bh1);
                mma_bf16(dacc[nt], Ahi[ks], bl0, bl1);
            }
        }
        #pragma unroll
        for (int nt = 0; nt < 2; nt++) {
            int nb = nt * 8 + 2 * t4;
            *(float2*)&s_sd[SD(khb, M0 + g,     nb)] = make_float2(dacc[nt][0], dacc[nt][1]);
            *(float2*)&s_sd[SD(khb, M0 + g + 8, nb)] = make_float2(dacc[nt][2], dacc[nt][3]);
        }
        __syncthreads();   // all slabs visible

        // ---- gate: thread owns (col gc, b = 2kq+j) ----
        #pragma unroll
        for (int j = 0; j < 2; j++) {
            int b = kq * 2 + j;
            float Apre = s_sd[SD(0, cl, b)] + s_sd[SD(1, cl, b)] + bA;
            float Hpre = s_sd[SD(0, 64 + cl, b)] + s_sd[SD(1, 64 + cl, b)] + bH;
            float xw = (s_sdx[SDX(0, cl, b)] + s_sdx[SDX(1, cl, b)])
                     + (s_sdx[SDX(2, cl, b)] + s_sdx[SDX(3, cl, b)]);
            float alpha = 1.0f / (1.0f + expf(-Apre));
            float hs    = (exp2f(alpha * Hpre) - 1.0f) / alpha + alpha;
            float nh    = tanhf(xw + bX + hs);

            uint32_t oldw = cur[b * HROW + gc];
            uint32_t word;
            if (t < len2[j]) {
                s_hO[b * 64 + cl] = nh;
                word = packw(nh);
            } else {
                word = oldw;   // exact carry
            }
            uint32_t boff = nxtoff + (uint32_t)((b * HROW + gc) * 4);
            #pragma unroll
            for (int d = 0; d < CSIZE; d++)
                asm volatile("st.shared::cluster.b32 [%0], %1;"
                             :: "r"(rb[d] + boff), "r"(word) : "memory");
        }

        // ---- stage x(t+1) into next buffer (local only) ----
        {
            uint4 wv = make_uint4(packw(xp.x), packw(xp.y), packw(xp.z), packw(xp.w));
            *(uint4*)(nxt + wid * HROW + 256 + 4 * lane) = wv;
        }
        if (t + 2 < cap)
            xp = ((const float4*)(data + ((size_t)(t + 2) * BATCH + B0) * DIN))[tid];

        cluster_sync_();   // remote h stores + local x staging visible
    }

    // output (len >= 1 guarantees every (b, cl) written at t=0)
    #pragma unroll
    for (int j = 0; j < 2; j++) {
        int b = kq * 2 + j;
        out[(size_t)(B0 + b) * HIDN + gc] = s_hO[b * 64 + cl];
    }
}

extern "C" void kernel_launch(void* const* d_in, const int* in_sizes, int n_in,
                              void* d_out, int out_size)
{
    (void)in_sizes; (void)n_in; (void)out_size;
    const float* data    = (const float*)d_in[0];   // [1024,512,128]
    const float* ih_w    = (const float*)d_in[1];   // [256,128]
    const float* ih_b    = (const float*)d_in[2];   // [256]
    const float* hh_w    = (const float*)d_in[3];   // [512,256]
    const float* hh_b    = (const float*)d_in[4];   // [512]
    const int*   lengths = (const int*)d_in[5];     // [512]
    float*       out     = (float*)d_out;           // [1,512,256]

    cudaFuncSetAttribute(rnn_kernel,
                         cudaFuncAttributeMaxDynamicSharedMemorySize, SMEM_BYTES);
    rnn_kernel<<<NCTA, NT, SMEM_BYTES>>>(data, ih_w, ih_b, hh_w, hh_b, lengths, out);
}

// round 14
// speedup vs baseline: 2.7697x; 1.0580x over previous
#include <cuda_runtime.h>
#include <cuda_bf16.h>
#include <math.h>
#include <stdint.h>

#define BATCH 512
#define DIN   128
#define HIDN  256
#define CSIZE 4
#define NT    512
#define NCTA  128

#define ROWW  196                     /* u32 words per row: 128 h + 64 x + pad */
#define BUFW  (16 * ROWW)             /* words per buffer (16 rows)            */

/* byte layout */
#define OB_HI   0                     /* hi: 2 buf x BUFW words = 25088 B      */
#define OB_LO   25088                 /* lo: 25088 B                           */
#define OB_SD   50176                 /* f32 [2 kh][16 n][132 m] = 16896 B     */
#define OB_SDX  67072                 /* f32 [4 kp][16 n][68 m]  = 17408 B     */
#define SMEM_BYTES 84480

#define SD2(kh,n,m)  ((((kh)*16+(n))*132)+(m))
#define SDX2(kp,n,m) ((((kp)*16+(n))*68)+(m))

__device__ __forceinline__ uint32_t smem_u32(const void* p) {
    uint32_t a;
    asm("{ .reg .u64 t; cvta.to.shared.u64 t, %1; cvt.u32.u64 %0, t; }" : "=r"(a) : "l"(p));
    return a;
}
__device__ __forceinline__ void cluster_sync_() {
    asm volatile("barrier.cluster.arrive.aligned;" ::: "memory");
    asm volatile("barrier.cluster.wait.aligned;" ::: "memory");
}
__device__ __forceinline__ void mma_bf16(float* d, const uint32_t* a, uint32_t b0, uint32_t b1) {
    asm volatile(
        "mma.sync.aligned.m16n8k16.row.col.f32.bf16.bf16.f32 "
        "{%0,%1,%2,%3}, {%4,%5,%6,%7}, {%8,%9}, {%0,%1,%2,%3};"
        : "+f"(d[0]), "+f"(d[1]), "+f"(d[2]), "+f"(d[3])
        : "r"(a[0]), "r"(a[1]), "r"(a[2]), "r"(a[3]), "r"(b0), "r"(b1));
}
__device__ __forceinline__ unsigned short bfbits(__nv_bfloat16 v) {
    return *(unsigned short*)&v;
}
__device__ __forceinline__ float ex2_(float x) {
    float y; asm("ex2.approx.f32 %0, %1;" : "=f"(y) : "f"(x)); return y;
}
__device__ __forceinline__ float rcp_(float x) {
    float y; asm("rcp.approx.f32 %0, %1;" : "=f"(y) : "f"(x)); return y;
}
/* permute word index within 8-groups so B-frag (b0,b1) is one LDS.64:
   orig j=t4 -> 2*t4 ; orig j=4+t4 -> 2*t4+1 */
__device__ __forceinline__ int wperm(int w) {
    return (w & ~7) | ((w & 3) << 1) | ((w >> 2) & 1);
}
/* split float pair into hi/lo bf16 packed words */
__device__ __forceinline__ void split2(float2 v, uint32_t& whi, uint32_t& wlo) {
    __nv_bfloat16 h0 = __float2bfloat16(v.x), h1 = __float2bfloat16(v.y);
    __nv_bfloat16 l0 = __float2bfloat16(v.x - __bfloat162float(h0));
    __nv_bfloat16 l1 = __float2bfloat16(v.y - __bfloat162float(h1));
    whi = (uint32_t)bfbits(h0) | ((uint32_t)bfbits(h1) << 16);
    wlo = (uint32_t)bfbits(l0) | ((uint32_t)bfbits(l1) << 16);
}

__global__ __launch_bounds__(NT, 1) __cluster_dims__(CSIZE, 1, 1)
void rnn_kernel(const float* __restrict__ data,
                const float* __restrict__ ih_w,
                const float* __restrict__ ih_b,
                const float* __restrict__ hh_w,
                const float* __restrict__ hh_b,
                const int*   __restrict__ lengths,
                float*       __restrict__ out)
{
    extern __shared__ char smdyn[];
    uint32_t* s_hi  = (uint32_t*)(smdyn + OB_HI);
    uint32_t* s_lo  = (uint32_t*)(smdyn + OB_LO);
    float*    s_sd  = (float*)(smdyn + OB_SD);
    float*    s_sdx = (float*)(smdyn + OB_SDX);

    const int tid  = threadIdx.x;
    const int wid  = tid >> 5;
    const int lane = tid & 31;
    const int g    = lane >> 2;
    const int t4   = lane & 3;
    uint32_t r;
    asm("mov.u32 %0, %%cluster_ctarank;" : "=r"(r));
    const int B0  = (blockIdx.x >> 2) * 16;
    const int cl  = tid & 63;
    const int p   = cl & 31;                    // col-pair index 0..31
    const int row = (tid >> 6) + ((cl >> 5) << 3);  // owned batch row 0..15
    const int gc0 = (int)r * 64 + 2 * p;        // first owned global col (even)

    const int M0  = (wid >> 1) * 16;            // gate GEMM M slice
    const int khb = wid & 1;                    // gate GEMM K half
    const int K0c = khb * 128;
    const int xms = wid >> 2;                   // xw GEMM M slice
    const int xkp = wid & 3;                    // xw GEMM k-pair

    // ---- persistent A fragments (hh_w, bf16 hi/lo split) ----
    uint32_t Ahi[8][4], Alo[8][4];
    #pragma unroll
    for (int ks = 0; ks < 8; ks++) {
        #pragma unroll
        for (int rg = 0; rg < 4; rg++) {
            int m = M0 + g + ((rg & 1) ? 8 : 0);
            int c = K0c + ks * 16 + 2 * t4 + ((rg >= 2) ? 8 : 0);
            int grow = (m < 64) ? ((int)r * 64 + m) : (HIDN + (int)r * 64 + (m - 64));
            float w0 = hh_w[grow * HIDN + c];
            float w1 = hh_w[grow * HIDN + c + 1];
            __nv_bfloat16 h0 = __float2bfloat16(w0), h1 = __float2bfloat16(w1);
            __nv_bfloat16 l0 = __float2bfloat16(w0 - __bfloat162float(h0));
            __nv_bfloat16 l1 = __float2bfloat16(w1 - __bfloat162float(h1));
            Ahi[ks][rg] = (uint32_t)bfbits(h0) | ((uint32_t)bfbits(h1) << 16);
            Alo[ks][rg] = (uint32_t)bfbits(l0) | ((uint32_t)bfbits(l1) << 16);
        }
    }
    uint32_t Xhi[2][4], Xlo[2][4];
    #pragma unroll
    for (int kk = 0; kk < 2; kk++) {
        int ks = 2 * xkp + kk;
        #pragma unroll
        for (int rg = 0; rg < 4; rg++) {
            int m = 16 * xms + g + ((rg & 1) ? 8 : 0);
            int c = ks * 16 + 2 * t4 + ((rg >= 2) ? 8 : 0);
            float w0 = ih_w[((int)r * 64 + m) * DIN + c];
            float w1 = ih_w[((int)r * 64 + m) * DIN + c + 1];
            __nv_bfloat16 h0 = __float2bfloat16(w0), h1 = __float2bfloat16(w1);
            __nv_bfloat16 l0 = __float2bfloat16(w0 - __bfloat162float(h0));
            __nv_bfloat16 l1 = __float2bfloat16(w1 - __bfloat162float(h1));
            Xhi[kk][rg] = (uint32_t)bfbits(h0) | ((uint32_t)bfbits(h1) << 16);
            Xlo[kk][rg] = (uint32_t)bfbits(l0) | ((uint32_t)bfbits(l1) << 16);
        }
    }

    const float2 bA2 = *(const float2*)&hh_b[gc0];
    const float2 bH2 = *(const float2*)&hh_b[gc0 + HIDN];
    const float2 bX2 = *(const float2*)&ih_b[gc0];

    const int len = lengths[B0 + row];
    int cap = 1;
    for (int i = 0; i < 16; i++) cap = max(cap, lengths[B0 + i]);

    // zero hi+lo (adjacent: 2*2*BUFW words)
    for (int i = tid; i < 4 * BUFW; i += NT) s_hi[i] = 0u;

    const uint32_t smb = smem_u32(smdyn);
    uint32_t rb[CSIZE];
    #pragma unroll
    for (int d = 0; d < CSIZE; d++)
        asm("mapa.shared::cluster.u32 %0, %1, %2;" : "=r"(rb[d]) : "r"(smb), "r"(d));

    // x word positions (permuted) owned by this thread
    const int xpos0 = 128 + wperm(p);
    const int xpos1 = 128 + wperm(p + 32);
    const int hpos  = wperm((int)r * 32 + p);   // hidden word (2 cols) position

    // stage x(0) into buf0
    {
        const float* xr = data + (size_t)(B0 + row) * DIN;
        uint32_t whi, wlo;
        split2(*(const float2*)&xr[2 * p], whi, wlo);
        s_hi[row * ROWW + xpos0] = whi;  s_lo[row * ROWW + xpos0] = wlo;
        split2(*(const float2*)&xr[64 + 2 * p], whi, wlo);
        s_hi[row * ROWW + xpos1] = whi;  s_lo[row * ROWW + xpos1] = wlo;
    }
    float2 xpa, xpb;
    {
        const float* xr = data + ((size_t)BATCH + B0 + row) * DIN;
        xpa = *(const float2*)&xr[2 * p];
        xpb = *(const float2*)&xr[64 + 2 * p];
    }

    float2 hout = make_float2(0.f, 0.f);

    __syncthreads();
    cluster_sync_();   // zeros + x0 visible cluster-wide

    for (int t = 0; t < cap; ++t) {
        const uint32_t cb = (uint32_t)((t & 1) * BUFW);
        const uint32_t nb = (uint32_t)(((t + 1) & 1) * BUFW);

        // ================= xw GEMM (K=128, x region) =================
        {
            float xacc[2][4];
            #pragma unroll
            for (int nt = 0; nt < 2; nt++)
                #pragma unroll
                for (int i = 0; i < 4; i++) xacc[nt][i] = 0.f;
            #pragma unroll
            for (int kk = 0; kk < 2; kk++) {
                int ks = 2 * xkp + kk;
                #pragma unroll
                for (int nt = 0; nt < 2; nt++) {
                    uint32_t w = cb + (uint32_t)((nt * 8 + g) * ROWW + 128 + ks * 8 + 2 * t4);
                    uint2 bh = *(const uint2*)&s_hi[w];
                    uint2 bl = *(const uint2*)&s_lo[w];
                    mma_bf16(xacc[nt], Xhi[kk], bh.x, bh.y);
                    mma_bf16(xacc[nt], Xlo[kk], bh.x, bh.y);
                    mma_bf16(xacc[nt], Xhi[kk], bl.x, bl.y);
                }
            }
            #pragma unroll
            for (int nt = 0; nt < 2; nt++) {
                int n0 = nt * 8 + 2 * t4;
                s_sdx[SDX2(xkp, n0,     16 * xms + g)]     = xacc[nt][0];
                s_sdx[SDX2(xkp, n0 + 1, 16 * xms + g)]     = xacc[nt][1];
                s_sdx[SDX2(xkp, n0,     16 * xms + g + 8)] = xacc[nt][2];
                s_sdx[SDX2(xkp, n0 + 1, 16 * xms + g + 8)] = xacc[nt][3];
            }
        }

        // ================= gate GEMM (K=256, h region) =================
        {
            float dacc[2][4];
            #pragma unroll
            for (int nt = 0; nt < 2; nt++)
                #pragma unroll
                for (int i = 0; i < 4; i++) dacc[nt][i] = 0.f;
            #pragma unroll
            for (int ks = 0; ks < 8; ks++) {
                #pragma unroll
                for (int nt = 0; nt < 2; nt++) {
                    uint32_t w = cb + (uint32_t)((nt * 8 + g) * ROWW + khb * 64 + ks * 8 + 2 * t4);
                    uint2 bh = *(const uint2*)&s_hi[w];
                    uint2 bl = *(const uint2*)&s_lo[w];
                    mma_bf16(dacc[nt], Ahi[ks], bh.x, bh.y);
                    mma_bf16(dacc[nt], Alo[ks], bh.x, bh.y);
                    mma_bf16(dacc[nt], Ahi[ks], bl.x, bl.y);
                }
            }
            #pragma unroll
            for (int nt = 0; nt < 2; nt++) {
                int n0 = nt * 8 + 2 * t4;
                s_sd[SD2(khb, n0,     M0 + g)]     = dacc[nt][0];
                s_sd[SD2(khb, n0 + 1, M0 + g)]     = dacc[nt][1];
                s_sd[SD2(khb, n0,     M0 + g + 8)] = dacc[nt][2];
                s_sd[SD2(khb, n0 + 1, M0 + g + 8)] = dacc[nt][3];
            }
        }
        __syncthreads();   // slabs visible

        // ================= gate: (row, cols 2p, 2p+1) =================
        {
            float2 vA0 = *(const float2*)&s_sd[SD2(0, row, 2 * p)];
            float2 vA1 = *(const float2*)&s_sd[SD2(1, row, 2 * p)];
            float2 vH0 = *(const float2*)&s_sd[SD2(0, row, 64 + 2 * p)];
            float2 vH1 = *(const float2*)&s_sd[SD2(1, row, 64 + 2 * p)];
            float2 x0 = *(const float2*)&s_sdx[SDX2(0, row, 2 * p)];
            float2 x1 = *(const float2*)&s_sdx[SDX2(1, row, 2 * p)];
            float2 x2 = *(const float2*)&s_sdx[SDX2(2, row, 2 * p)];
            float2 x3 = *(const float2*)&s_sdx[SDX2(3, row, 2 * p)];

            uint32_t whi, wlo;
            if (t < len) {
                float A0 = vA0.x + vA1.x + bA2.x;
                float A1 = vA0.y + vA1.y + bA2.y;
                float H0 = vH0.x + vH1.x + bH2.x;
                float H1 = vH0.y + vH1.y + bH2.y;
                float xw0 = (x0.x + x1.x) + (x2.x + x3.x) + bX2.x;
                float xw1 = (x0.y + x1.y) + (x2.y + x3.y) + bX2.y;

                float al0 = rcp_(1.0f + ex2_(-1.442695041f * A0));
                float al1 = rcp_(1.0f + ex2_(-1.442695041f * A1));
                float hs0 = (ex2_(al0 * H0) - 1.0f) * rcp_(al0) + al0;
                float hs1 = (ex2_(al1 * H1) - 1.0f) * rcp_(al1) + al1;
                float z0  = xw0 + hs0;
                float z1  = xw1 + hs1;
                float nh0 = 1.0f - 2.0f * rcp_(ex2_(2.885390082f * z0) + 1.0f);
                float nh1 = 1.0f - 2.0f * rcp_(ex2_(2.885390082f * z1) + 1.0f);
                hout = make_float2(nh0, nh1);
                split2(hout, whi, wlo);
            } else {
                whi = s_hi[cb + (uint32_t)(row * ROWW + hpos)];
                wlo = s_lo[cb + (uint32_t)(row * ROWW + hpos)];
            }
            uint32_t wi = nb + (uint32_t)(row * ROWW + hpos);
            s_hi[wi] = whi;                       // local copy
            s_lo[wi] = wlo;
            uint32_t boff = wi * 4;
            #pragma unroll
            for (int d = 0; d < CSIZE; d++) {
                if (d != (int)r) {
                    asm volatile("st.shared::cluster.b32 [%0], %1;"
                                 :: "r"(rb[d] + OB_HI + boff), "r"(whi) : "memory");
                    asm volatile("st.shared::cluster.b32 [%0], %1;"
                                 :: "r"(rb[d] + OB_LO + boff), "r"(wlo) : "memory");
                }
            }
        }

        // ---- stage x(t+1) into next buffer (local) ----
        {
            uint32_t whi, wlo;
            split2(xpa, whi, wlo);
            s_hi[nb + (uint32_t)(row * ROWW + xpos0)] = whi;
            s_lo[nb + (uint32_t)(row * ROWW + xpos0)] = wlo;
            split2(xpb, whi, wlo);
            s_hi[nb + (uint32_t)(row * ROWW + xpos1)] = whi;
            s_lo[nb + (uint32_t)(row * ROWW + xpos1)] = wlo;
        }
        if (t + 2 < cap) {
            const float* xr = data + ((size_t)(t + 2) * BATCH + B0 + row) * DIN;
            xpa = *(const float2*)&xr[2 * p];
            xpb = *(const float2*)&xr[64 + 2 * p];
        }

        cluster_sync_();   // arrive=release: all stores visible cluster-wide
    }

    *(float2*)&out[(size_t)(B0 + row) * HIDN + gc0] = hout;
}

extern "C" void kernel_launch(void* const* d_in, const int* in_sizes, int n_in,
                              void* d_out, int out_size)
{
    (void)in_sizes; (void)n_in; (void)out_size;
    const float* data    = (const float*)d_in[0];   // [1024,512,128]
    const float* ih_w    = (const float*)d_in[1];   // [256,128]
    const float* ih_b    = (const float*)d_in[2];   // [256]
    const float* hh_w    = (const float*)d_in[3];   // [512,256]
    const float* hh_b    = (const float*)d_in[4];   // [512]
    const int*   lengths = (const int*)d_in[5];     // [512]
    float*       out     = (float*)d_out;           // [1,512,256]

    cudaFuncSetAttribute(rnn_kernel,
                         cudaFuncAttributeMaxDynamicSharedMemorySize, SMEM_BYTES);
    rnn_kernel<<<NCTA, NT, SMEM_BYTES>>>(data, ih_w, ih_b, hh_w, hh_b, lengths, out);
}